// round 9
// baseline (speedup 1.0000x reference)
#include <cuda_runtime.h>
#include <cuda_fp16.h>
#include <cstdint>

#define NB 32
#define CC 512
#define CI 256
#define NN 1024
#define EPSF 1e-5f

// ---------------- scratch (device globals; no allocations allowed) ----------
__device__ __align__(128) __half d_W3[768 * CC];                   // rows: 0-255 Wt, 256-511 Wp, 512-767 Wg
__device__ __align__(128) __half d_Wzh[CC * CI];
__device__ __align__(128) __half d_xp[(size_t)NB * NN * CC];       // x^T [b][n][c]
__device__ __align__(128) __half d_th[(size_t)NB * NN * CI];       // theta [b][n][c]
__device__ __align__(128) __half d_ph[(size_t)NB * NN * CI];       // phi   [b][m][c]
__device__ __align__(128) __half d_gp[(size_t)NB * CI * NN];       // g [b][c][m]
__device__ __align__(128) __half d_fh[(size_t)NB * NN * NN];       // logits fp16 [b][n][m]
__device__ __align__(128) __half d_P[(size_t)NB * NN * NN];        // attn [b][n][m]
__device__ __align__(128) __half d_y[(size_t)NB * NN * CI];        // y [b][n][c]
__device__ __align__(128) __half d_wyh[(size_t)NB * CC * NN];      // w_y fp16 [b][c][n]
__device__ float d_mean[CC], d_rstd[CC];

// ---------------- PTX helpers ----------------------------------------------
__device__ __forceinline__ uint32_t smem_u32_of(const void* p) {
    uint32_t a;
    asm("{ .reg .u64 t; cvta.to.shared.u64 t, %1; cvt.u32.u64 %0, t; }" : "=r"(a) : "l"(p));
    return a;
}
#define CP_ASYNC16(dst, src) \
    asm volatile("cp.async.cg.shared.global [%0], [%1], 16;" :: "r"(dst), "l"(src))
#define CP_COMMIT() asm volatile("cp.async.commit_group;" ::: "memory")
#define CP_WAIT1()  asm volatile("cp.async.wait_group 1;" ::: "memory")
#define LDSM4(r0, r1, r2, r3, addr) \
    asm volatile("ldmatrix.sync.aligned.m8n8.x4.shared.b16 {%0,%1,%2,%3}, [%4];" \
                 : "=r"(r0), "=r"(r1), "=r"(r2), "=r"(r3) : "r"(addr))
#define MMA16816(d, a, b0, b1) \
    asm volatile("mma.sync.aligned.m16n8k16.row.col.f32.f16.f16.f32 " \
                 "{%0,%1,%2,%3}, {%4,%5,%6,%7}, {%8,%9}, {%0,%1,%2,%3};" \
                 : "+f"((d)[0]), "+f"((d)[1]), "+f"((d)[2]), "+f"((d)[3]) \
                 : "r"((a)[0]), "r"((a)[1]), "r"((a)[2]), "r"((a)[3]), "r"(b0), "r"(b1))

// ---------------- GEMM core (R5/R7 config) ----------------------------------
// C[128 x 128] = A[128 x K] . B[128 x K]^T,  A/B row-major K-contiguous fp16.
// 256 threads, warp grid 2(M) x 4(N), warp tile 64x32, BK=64, 3-stage cp.async.
#define BK 64
#define STAGES 3
#define STAGE_B 32768          // A 16KB + B 16KB
#define SMEM_GEMM (STAGES * STAGE_B)

struct Acc { float c[4][4][4]; };

__device__ __forceinline__ void load_stage(char* sm, int s,
                                           const __half* A, int lda,
                                           const __half* B, int ldb,
                                           int kt, int tid) {
    const char* ag = (const char*)(A + (size_t)kt * BK);
    const char* bg = (const char*)(B + (size_t)kt * BK);
    uint32_t sa = smem_u32_of(sm + s * STAGE_B);
    uint32_t sb = sa + 16384;
    #pragma unroll
    for (int i = 0; i < 4; i++) {
        int L = tid + i * 256;
        int r = L >> 3, c8 = L & 7;
        uint32_t off = (uint32_t)(r * 128 + ((c8 ^ (r & 7)) * 16));
        CP_ASYNC16(sa + off, ag + (size_t)r * lda * 2 + c8 * 16);
        CP_ASYNC16(sb + off, bg + (size_t)r * ldb * 2 + c8 * 16);
    }
    CP_COMMIT();
}

__device__ __forceinline__ void compute_stage(char* sm, int s, Acc& acc,
                                              int wm, int wn, int lane) {
    uint32_t sa = smem_u32_of(sm + s * STAGE_B);
    uint32_t sb = sa + 16384;
    const int lr = lane & 15, lc = lane >> 4;
    #pragma unroll
    for (int ks = 0; ks < 4; ks++) {
        uint32_t a[4][4], bf[2][4];
        const int c8 = ks * 2 + lc;
        #pragma unroll
        for (int mi = 0; mi < 4; mi++) {
            int row = wm * 64 + mi * 16 + lr;
            uint32_t addr = sa + (uint32_t)(row * 128 + ((c8 ^ (row & 7)) * 16));
            LDSM4(a[mi][0], a[mi][1], a[mi][2], a[mi][3], addr);
        }
        #pragma unroll
        for (int nj = 0; nj < 2; nj++) {
            int row = wn * 32 + nj * 16 + lr;
            uint32_t addr = sb + (uint32_t)(row * 128 + ((c8 ^ (row & 7)) * 16));
            LDSM4(bf[nj][0], bf[nj][1], bf[nj][2], bf[nj][3], addr);
        }
        #pragma unroll
        for (int mi = 0; mi < 4; mi++)
            #pragma unroll
            for (int ni = 0; ni < 4; ni++)
                MMA16816(acc.c[mi][ni], a[mi], bf[ni >> 1][ni & 1], bf[ni >> 1][(ni & 1) + 2]);
    }
}

__device__ __forceinline__ void gemm_main(Acc& acc, char* sm,
                                          const __half* A, int lda,
                                          const __half* B, int ldb, int K) {
    const int tid = threadIdx.x;
    const int lane = tid & 31, wid = tid >> 5;
    const int wm = wid & 1, wn = wid >> 1;
    #pragma unroll
    for (int mi = 0; mi < 4; mi++)
        #pragma unroll
        for (int ni = 0; ni < 4; ni++)
            #pragma unroll
            for (int k = 0; k < 4; k++) acc.c[mi][ni][k] = 0.f;

    const int nk = K / BK;
    #pragma unroll
    for (int s = 0; s < STAGES - 1; s++) load_stage(sm, s, A, lda, B, ldb, s, tid);
    for (int k = 0; k < nk; k++) {
        CP_WAIT1();
        __syncthreads();
        if (k + STAGES - 1 < nk)
            load_stage(sm, (k + STAGES - 1) % STAGES, A, lda, B, ldb, k + STAGES - 1, tid);
        compute_stage(sm, k % STAGES, acc, wm, wn, lane);
    }
}

// thread's accum coordinates: row = wm*64 + mi*16 + (lane>>2) + h*8
//                             col = wn*32 + ni*8 + (lane&3)*2
#define EPI_SETUP() \
    const int lane = threadIdx.x & 31, wid = threadIdx.x >> 5; \
    const int wm = wid & 1, wn = wid >> 1; (void)wm; (void)wn;

// ---------------------------------------------------------------------------
// GEMM kernels
// ---------------------------------------------------------------------------
// theta/phi projection: C[n, o] = x'[n,:].W3[o,:], K=512, + bias. o0 in {0..384}
__global__ void __launch_bounds__(256) proj_thphi(
    const float* __restrict__ bt, const float* __restrict__ bp)
{
    extern __shared__ char sm[];
    const int b = blockIdx.z, n0 = blockIdx.y * 128, o0 = blockIdx.x * 128;
    Acc acc;
    gemm_main(acc, sm,
              d_xp + ((size_t)b * NN + n0) * CC, CC,
              d_W3 + (size_t)o0 * CC, CC, CC);
    EPI_SETUP();
    const bool is_t = (o0 < 256);
    const float* bias = is_t ? bt : bp;
    __half* T = is_t ? d_th : d_ph;
    #pragma unroll
    for (int mi = 0; mi < 4; mi++) {
        #pragma unroll
        for (int ni = 0; ni < 4; ni++) {
            const int r = wm * 64 + mi * 16 + (lane >> 2);
            const int ci = (o0 & 255) + wn * 32 + ni * 8 + (lane & 3) * 2;
            const float2 bv = *(const float2*)&bias[ci];
            #pragma unroll
            for (int h = 0; h < 2; h++) {
                const int n = n0 + r + h * 8;
                __half2 hv = __floats2half2_rn(acc.c[mi][ni][h * 2] + bv.x,
                                               acc.c[mi][ni][h * 2 + 1] + bv.y);
                *(__half2*)(T + ((size_t)b * NN + n) * CI + ci) = hv;
            }
        }
    }
}

// g projection: C[o, n] = Wg[o,:].x'[n,:], K=512, + bias
__global__ void __launch_bounds__(256) proj_g(const float* __restrict__ bg)
{
    extern __shared__ char sm[];
    const int b = blockIdx.z, o0 = blockIdx.y * 128, n0 = blockIdx.x * 128;
    Acc acc;
    gemm_main(acc, sm,
              d_W3 + (size_t)(512 + o0) * CC, CC,
              d_xp + ((size_t)b * NN + n0) * CC, CC, CC);
    EPI_SETUP();
    #pragma unroll
    for (int mi = 0; mi < 4; mi++) {
        #pragma unroll
        for (int ni = 0; ni < 4; ni++) {
            const int r = wm * 64 + mi * 16 + (lane >> 2);
            const int col = wn * 32 + ni * 8 + (lane & 3) * 2;
            #pragma unroll
            for (int h = 0; h < 2; h++) {
                const int o = o0 + r + h * 8;
                const float bvv = bg[o];
                __half2 hv = __floats2half2_rn(acc.c[mi][ni][h * 2] + bvv,
                                               acc.c[mi][ni][h * 2 + 1] + bvv);
                *(__half2*)(d_gp + ((size_t)b * CI + o) * NN + n0 + col) = hv;
            }
        }
    }
}

// logits: C[n, m] = theta[n,:].phi[m,:], K=256, fp16 out
__global__ void __launch_bounds__(256) fgemm(void)
{
    extern __shared__ char sm[];
    const int b = blockIdx.z, n0 = blockIdx.y * 128, m0 = blockIdx.x * 128;
    Acc acc;
    gemm_main(acc, sm,
              d_th + ((size_t)b * NN + n0) * CI, CI,
              d_ph + ((size_t)b * NN + m0) * CI, CI, CI);
    EPI_SETUP();
    #pragma unroll
    for (int mi = 0; mi < 4; mi++) {
        #pragma unroll
        for (int ni = 0; ni < 4; ni++) {
            const int r = wm * 64 + mi * 16 + (lane >> 2);
            const int col = wn * 32 + ni * 8 + (lane & 3) * 2;
            #pragma unroll
            for (int h = 0; h < 2; h++) {
                const int n = n0 + r + h * 8;
                __half2 hv = __floats2half2_rn(acc.c[mi][ni][h * 2],
                                               acc.c[mi][ni][h * 2 + 1]);
                *(__half2*)(d_fh + ((size_t)b * NN + n) * NN + m0 + col) = hv;
            }
        }
    }
}

// y: C[n, c] = P[n,:].g[c,:], K=1024
__global__ void __launch_bounds__(256) ygemm(void)
{
    extern __shared__ char sm[];
    const int b = blockIdx.z, n0 = blockIdx.y * 128, c0 = blockIdx.x * 128;
    Acc acc;
    gemm_main(acc, sm,
              d_P + ((size_t)b * NN + n0) * NN, NN,
              d_gp + ((size_t)b * CI + c0) * NN, NN, NN);
    EPI_SETUP();
    #pragma unroll
    for (int mi = 0; mi < 4; mi++) {
        #pragma unroll
        for (int ni = 0; ni < 4; ni++) {
            const int r = wm * 64 + mi * 16 + (lane >> 2);
            const int col = wn * 32 + ni * 8 + (lane & 3) * 2;
            #pragma unroll
            for (int h = 0; h < 2; h++) {
                const int n = n0 + r + h * 8;
                __half2 hv = __floats2half2_rn(acc.c[mi][ni][h * 2],
                                               acc.c[mi][ni][h * 2 + 1]);
                *(__half2*)(d_y + ((size_t)b * NN + n) * CI + c0 + col) = hv;
            }
        }
    }
}

// wz: C[o, n] = Wz[o,:].y[n,:], K=256, + bias, fp16 out
__global__ void __launch_bounds__(256) zgemm(const float* __restrict__ bz)
{
    extern __shared__ char sm[];
    const int b = blockIdx.z, o0 = blockIdx.y * 128, n0 = blockIdx.x * 128;
    Acc acc;
    gemm_main(acc, sm,
              d_Wzh + (size_t)o0 * CI, CI,
              d_y + ((size_t)b * NN + n0) * CI, CI, CI);
    EPI_SETUP();
    #pragma unroll
    for (int mi = 0; mi < 4; mi++) {
        #pragma unroll
        for (int ni = 0; ni < 4; ni++) {
            const int r = wm * 64 + mi * 16 + (lane >> 2);
            const int col = wn * 32 + ni * 8 + (lane & 3) * 2;
            #pragma unroll
            for (int h = 0; h < 2; h++) {
                const int o = o0 + r + h * 8;
                const float bvv = bz[o];
                __half2 hv = __floats2half2_rn(acc.c[mi][ni][h * 2] + bvv,
                                               acc.c[mi][ni][h * 2 + 1] + bvv);
                *(__half2*)(d_wyh + ((size_t)b * CC + o) * NN + n0 + col) = hv;
            }
        }
    }
}

// ---------------------------------------------------------------------------
// Conversion kernels
// ---------------------------------------------------------------------------
__global__ void __launch_bounds__(256) convert_w(
    const float* __restrict__ Wg, const float* __restrict__ Wt, const float* __restrict__ Wp)
{
    int idx = blockIdx.x * 256 + threadIdx.x;   // 768*512
    int row = idx >> 9, c = idx & 511;
    float v = (row < 256) ? Wt[row * CC + c]
            : (row < 512) ? Wp[(row - 256) * CC + c]
                          : Wg[(row - 512) * CC + c];
    d_W3[idx] = __float2half_rn(v);
}

__global__ void __launch_bounds__(256) convert_wz(const float* __restrict__ Wz)
{
    int idx = blockIdx.x * 256 + threadIdx.x;   // 512*256
    d_Wzh[idx] = __float2half_rn(Wz[idx]);
}

// x[b][c][n] fp32 -> d_xp[b][n][c] fp16 (32x32 smem transpose)
__global__ void __launch_bounds__(256) convert_x(const float* __restrict__ x)
{
    __shared__ float t[32][33];
    const int n0 = blockIdx.x * 32, c0 = blockIdx.y * 32, b = blockIdx.z;
    const int tx = threadIdx.x, ty = threadIdx.y;   // (32, 8)
    #pragma unroll
    for (int i = 0; i < 4; i++)
        t[ty + i * 8][tx] = x[((size_t)b * CC + c0 + ty + i * 8) * NN + n0 + tx];
    __syncthreads();
    #pragma unroll
    for (int i = 0; i < 4; i++) {
        const int n = n0 + ty + i * 8, c = c0 + tx;
        d_xp[((size_t)b * NN + n) * CC + c] = __float2half_rn(t[tx][ty + i * 8]);
    }
}

// ---------------------------------------------------------------------------
// Softmax over m (1024): d_fh fp16 -> d_P fp16
// ---------------------------------------------------------------------------
__global__ void __launch_bounds__(256) softmax_kernel()
{
    const size_t row = blockIdx.x;
    const __half* p = d_fh + row * NN;
    const int tid = threadIdx.x;
    const int lane = tid & 31, warp = tid >> 5;

    union { __half2 h2[2]; uint2 u; } In;
    In.u = ((const uint2*)p)[tid];
    float4 v;
    {
        float2 a = __half22float2(In.h2[0]);
        float2 c = __half22float2(In.h2[1]);
        v = make_float4(a.x, a.y, c.x, c.y);
    }
    float m = fmaxf(fmaxf(v.x, v.y), fmaxf(v.z, v.w));
    #pragma unroll
    for (int off = 16; off; off >>= 1) m = fmaxf(m, __shfl_xor_sync(~0u, m, off));
    __shared__ float redm[8];
    if (lane == 0) redm[warp] = m;
    __syncthreads();
    float bm = redm[0];
    #pragma unroll
    for (int i = 1; i < 8; i++) bm = fmaxf(bm, redm[i]);

    v.x = expf(v.x - bm); v.y = expf(v.y - bm);
    v.z = expf(v.z - bm); v.w = expf(v.w - bm);
    float s = v.x + v.y + v.z + v.w;
    #pragma unroll
    for (int off = 16; off; off >>= 1) s += __shfl_xor_sync(~0u, s, off);
    __shared__ float reds[8];
    if (lane == 0) reds[warp] = s;
    __syncthreads();
    float bs = 0.f;
    #pragma unroll
    for (int i = 0; i < 8; i++) bs += reds[i];
    float inv = 1.f / bs;

    union { __half2 h2[2]; uint2 u; } U;
    U.h2[0] = __floats2half2_rn(v.x * inv, v.y * inv);
    U.h2[1] = __floats2half2_rn(v.z * inv, v.w * inv);
    ((uint2*)(d_P + row * NN))[tid] = U.u;
}

// ---------------------------------------------------------------------------
// BN statistics + final fuse (fp16 w_y)
// ---------------------------------------------------------------------------
__global__ void __launch_bounds__(256) bn_stats_kernel()
{
    const int ch = blockIdx.x;
    const int tid = threadIdx.x;
    float s = 0.f, s2 = 0.f;
    const __half* base = d_wyh;
    for (int i = tid; i < NB * NN / 2; i += 256) {
        int b = i / 512, n2 = i % 512;
        __half2 hv = *(const __half2*)(base + ((size_t)b * CC + ch) * NN + n2 * 2);
        float2 f2 = __half22float2(hv);
        s += f2.x + f2.y; s2 += f2.x * f2.x + f2.y * f2.y;
    }
    #pragma unroll
    for (int off = 16; off; off >>= 1) {
        s  += __shfl_xor_sync(~0u, s,  off);
        s2 += __shfl_xor_sync(~0u, s2, off);
    }
    __shared__ float rs[8], rs2[8];
    if ((tid & 31) == 0) { rs[tid >> 5] = s; rs2[tid >> 5] = s2; }
    __syncthreads();
    if (tid == 0) {
        float ts = 0.f, ts2 = 0.f;
        #pragma unroll
        for (int i = 0; i < 8; i++) { ts += rs[i]; ts2 += rs2[i]; }
        const float invM = 1.f / (float)(NB * NN);
        float mean = ts * invM;
        float var  = ts2 * invM - mean * mean;
        d_mean[ch] = mean;
        d_rstd[ch] = rsqrtf(var + EPSF);
    }
}

__global__ void __launch_bounds__(256) final_kernel(
    const float* __restrict__ x,
    const float* __restrict__ gamma, const float* __restrict__ beta,
    float* __restrict__ out)
{
    size_t i4 = (size_t)blockIdx.x * 256 + threadIdx.x;    // 4-element chunk index
    int c = (int)((i4 >> 8) & 511);
    float scale = d_rstd[c] * gamma[c];
    float shift = beta[c] - d_mean[c] * scale;
    union { __half2 h2[2]; uint2 u; } W;
    W.u = ((const uint2*)d_wyh)[i4];
    float2 w01 = __half22float2(W.h2[0]);
    float2 w23 = __half22float2(W.h2[1]);
    float4 xv = ((const float4*)x)[i4];
    float4 o;
    o.x = fmaf(w01.x, scale, shift) + xv.x;
    o.y = fmaf(w01.y, scale, shift) + xv.y;
    o.z = fmaf(w23.x, scale, shift) + xv.z;
    o.w = fmaf(w23.y, scale, shift) + xv.w;
    ((float4*)out)[i4] = o;
}

// ---------------------------------------------------------------------------
extern "C" void kernel_launch(void* const* d_in, const int* in_sizes, int n_in,
                              void* d_out, int out_size)
{
    (void)in_sizes; (void)n_in; (void)out_size;
    const float* x     = (const float*)d_in[0];
    const float* Wg    = (const float*)d_in[1];
    const float* bg    = (const float*)d_in[2];
    const float* Wt    = (const float*)d_in[3];
    const float* bt    = (const float*)d_in[4];
    const float* Wp    = (const float*)d_in[5];
    const float* bp    = (const float*)d_in[6];
    const float* Wz    = (const float*)d_in[7];
    const float* bz    = (const float*)d_in[8];
    const float* gamma = (const float*)d_in[9];
    const float* beta  = (const float*)d_in[10];
    float* out = (float*)d_out;

    cudaFuncSetAttribute(proj_thphi, cudaFuncAttributeMaxDynamicSharedMemorySize, SMEM_GEMM);
    cudaFuncSetAttribute(proj_g,     cudaFuncAttributeMaxDynamicSharedMemorySize, SMEM_GEMM);
    cudaFuncSetAttribute(fgemm,      cudaFuncAttributeMaxDynamicSharedMemorySize, SMEM_GEMM);
    cudaFuncSetAttribute(ygemm,      cudaFuncAttributeMaxDynamicSharedMemorySize, SMEM_GEMM);
    cudaFuncSetAttribute(zgemm,      cudaFuncAttributeMaxDynamicSharedMemorySize, SMEM_GEMM);

    dim3 blk(256);
    convert_w<<<768 * 512 / 256, blk>>>(Wg, Wt, Wp);
    convert_wz<<<512 * 256 / 256, blk>>>(Wz);
    convert_x<<<dim3(NN / 32, CC / 32, NB), dim3(32, 8)>>>(x);

    proj_thphi<<<dim3(4, 8, NB), blk, SMEM_GEMM>>>(bt, bp);
    proj_g<<<dim3(8, 2, NB), blk, SMEM_GEMM>>>(bg);
    fgemm<<<dim3(8, 8, NB), blk, SMEM_GEMM>>>();
    softmax_kernel<<<NB * NN, blk>>>();
    ygemm<<<dim3(2, 8, NB), blk, SMEM_GEMM>>>();
    zgemm<<<dim3(8, 4, NB), blk, SMEM_GEMM>>>(bz);

    bn_stats_kernel<<<CC, blk>>>();
    final_kernel<<<(NB * CC * NN / 4) / 256, blk>>>(x, gamma, beta, out);
}

// round 10
// speedup vs baseline: 1.4934x; 1.4934x over previous
#include <cuda_runtime.h>
#include <cuda_fp16.h>
#include <cstdint>

#define NB 32
#define CC 512
#define CI 256
#define NN 1024
#define EPSF 1e-5f

// ---------------- scratch (device globals; no allocations allowed) ----------
__device__ __align__(128) __half d_W3[768 * CC];                   // rows: 0-255 Wt, 256-511 Wp, 512-767 Wg
__device__ __align__(128) __half d_Wzh[CC * CI];
__device__ __align__(128) __half d_xp[(size_t)NB * NN * CC];       // x^T [b][n][c]
__device__ __align__(128) __half d_th[(size_t)NB * NN * CI];       // theta [b][n][c]
__device__ __align__(128) __half d_ph[(size_t)NB * NN * CI];       // phi   [b][m][c]
__device__ __align__(128) __half d_gp[(size_t)NB * CI * NN];       // g [b][c][m]
__device__ __align__(128) __half d_fh[(size_t)NB * NN * NN];       // logits fp16 [b][n][m]
__device__ __align__(128) __half d_P[(size_t)NB * NN * NN];        // attn [b][n][m]
__device__ __align__(128) __half d_y[(size_t)NB * NN * CI];        // y [b][n][c]
__device__ __align__(128) __half d_wyh[(size_t)NB * CC * NN];      // w_y fp16 [b][c][n]
__device__ float d_mean[CC], d_rstd[CC];

// ---------------- PTX helpers ----------------------------------------------
__device__ __forceinline__ uint32_t smem_u32_of(const void* p) {
    uint32_t a;
    asm("{ .reg .u64 t; cvta.to.shared.u64 t, %1; cvt.u32.u64 %0, t; }" : "=r"(a) : "l"(p));
    return a;
}
#define CP_ASYNC16(dst, src) \
    asm volatile("cp.async.cg.shared.global [%0], [%1], 16;" :: "r"(dst), "l"(src))
#define CP_COMMIT() asm volatile("cp.async.commit_group;" ::: "memory")
#define CP_WAIT1()  asm volatile("cp.async.wait_group 1;" ::: "memory")
#define LDSM4(r0, r1, r2, r3, addr) \
    asm volatile("ldmatrix.sync.aligned.m8n8.x4.shared.b16 {%0,%1,%2,%3}, [%4];" \
                 : "=r"(r0), "=r"(r1), "=r"(r2), "=r"(r3) : "r"(addr))
#define MMA16816(d, a, b0, b1) \
    asm volatile("mma.sync.aligned.m16n8k16.row.col.f32.f16.f16.f32 " \
                 "{%0,%1,%2,%3}, {%4,%5,%6,%7}, {%8,%9}, {%0,%1,%2,%3};" \
                 : "+f"((d)[0]), "+f"((d)[1]), "+f"((d)[2]), "+f"((d)[3]) \
                 : "r"((a)[0]), "r"((a)[1]), "r"((a)[2]), "r"((a)[3]), "r"(b0), "r"(b1))

// ---------------- GEMM core (R5/R7 config) ----------------------------------
// C[128 x 128] = A[128 x K] . B[128 x K]^T,  A/B row-major K-contiguous fp16.
// 256 threads, warp grid 2(M) x 4(N), warp tile 64x32, BK=64, 3-stage cp.async.
#define BK 64
#define STAGES 3
#define STAGE_B 32768          // A 16KB + B 16KB
#define SMEM_GEMM (STAGES * STAGE_B)

struct Acc { float c[4][4][4]; };

__device__ __forceinline__ void load_stage(char* sm, int s,
                                           const __half* A, int lda,
                                           const __half* B, int ldb,
                                           int kt, int tid) {
    const char* ag = (const char*)(A + (size_t)kt * BK);
    const char* bg = (const char*)(B + (size_t)kt * BK);
    uint32_t sa = smem_u32_of(sm + s * STAGE_B);
    uint32_t sb = sa + 16384;
    #pragma unroll
    for (int i = 0; i < 4; i++) {
        int L = tid + i * 256;
        int r = L >> 3, c8 = L & 7;
        uint32_t off = (uint32_t)(r * 128 + ((c8 ^ (r & 7)) * 16));
        CP_ASYNC16(sa + off, ag + (size_t)r * lda * 2 + c8 * 16);
        CP_ASYNC16(sb + off, bg + (size_t)r * ldb * 2 + c8 * 16);
    }
    CP_COMMIT();
}

__device__ __forceinline__ void compute_stage(char* sm, int s, Acc& acc,
                                              int wm, int wn, int lane) {
    uint32_t sa = smem_u32_of(sm + s * STAGE_B);
    uint32_t sb = sa + 16384;
    const int lr = lane & 15, lc = lane >> 4;
    #pragma unroll
    for (int ks = 0; ks < 4; ks++) {
        uint32_t a[4][4], bf[2][4];
        const int c8 = ks * 2 + lc;
        #pragma unroll
        for (int mi = 0; mi < 4; mi++) {
            int row = wm * 64 + mi * 16 + lr;
            uint32_t addr = sa + (uint32_t)(row * 128 + ((c8 ^ (row & 7)) * 16));
            LDSM4(a[mi][0], a[mi][1], a[mi][2], a[mi][3], addr);
        }
        #pragma unroll
        for (int nj = 0; nj < 2; nj++) {
            int row = wn * 32 + nj * 16 + lr;
            uint32_t addr = sb + (uint32_t)(row * 128 + ((c8 ^ (row & 7)) * 16));
            LDSM4(bf[nj][0], bf[nj][1], bf[nj][2], bf[nj][3], addr);
        }
        #pragma unroll
        for (int mi = 0; mi < 4; mi++)
            #pragma unroll
            for (int ni = 0; ni < 4; ni++)
                MMA16816(acc.c[mi][ni], a[mi], bf[ni >> 1][ni & 1], bf[ni >> 1][(ni & 1) + 2]);
    }
}

__device__ __forceinline__ void gemm_main(Acc& acc, char* sm,
                                          const __half* A, int lda,
                                          const __half* B, int ldb, int K) {
    const int tid = threadIdx.x;
    const int lane = tid & 31, wid = tid >> 5;
    const int wm = wid & 1, wn = wid >> 1;
    #pragma unroll
    for (int mi = 0; mi < 4; mi++)
        #pragma unroll
        for (int ni = 0; ni < 4; ni++)
            #pragma unroll
            for (int k = 0; k < 4; k++) acc.c[mi][ni][k] = 0.f;

    const int nk = K / BK;
    #pragma unroll
    for (int s = 0; s < STAGES - 1; s++) load_stage(sm, s, A, lda, B, ldb, s, tid);
    for (int k = 0; k < nk; k++) {
        CP_WAIT1();
        __syncthreads();
        if (k + STAGES - 1 < nk)
            load_stage(sm, (k + STAGES - 1) % STAGES, A, lda, B, ldb, k + STAGES - 1, tid);
        compute_stage(sm, k % STAGES, acc, wm, wn, lane);
    }
}

// thread's accum coordinates: row = wm*64 + mi*16 + (lane>>2) + h*8
//                             col = wn*32 + ni*8 + (lane&3)*2
#define EPI_SETUP() \
    const int lane = threadIdx.x & 31, wid = threadIdx.x >> 5; \
    const int wm = wid & 1, wn = wid >> 1; (void)wm; (void)wn;

// ---------------------------------------------------------------------------
// GEMM kernels
// ---------------------------------------------------------------------------
// Merged projection kernel. Tile id t = blockIdx.x:
//   t in [0, 32):  theta/phi: C[n, o] = x'[n,:].W3[o,:]; o0=(t>>3)*128, n0=(t&7)*128
//   t in [32, 48): g:         C[o, n] = Wg[o,:].x'[n,:]; o0=((t-32)>>3)*128, n0=((t-32)&7)*128
__global__ void __launch_bounds__(256) proj_all(
    const float* __restrict__ bt, const float* __restrict__ bp,
    const float* __restrict__ bg)
{
    extern __shared__ char sm[];
    const int b = blockIdx.z;
    const int t = blockIdx.x;
    Acc acc;
    EPI_SETUP();

    if (t < 32) {
        const int o0 = (t >> 3) * 128, n0 = (t & 7) * 128;
        gemm_main(acc, sm,
                  d_xp + ((size_t)b * NN + n0) * CC, CC,
                  d_W3 + (size_t)o0 * CC, CC, CC);
        const bool is_t = (o0 < 256);
        const float* bias = is_t ? bt : bp;
        __half* T = is_t ? d_th : d_ph;
        #pragma unroll
        for (int mi = 0; mi < 4; mi++) {
            #pragma unroll
            for (int ni = 0; ni < 4; ni++) {
                const int r = wm * 64 + mi * 16 + (lane >> 2);
                const int ci = (o0 & 255) + wn * 32 + ni * 8 + (lane & 3) * 2;
                const float2 bv = *(const float2*)&bias[ci];
                #pragma unroll
                for (int h = 0; h < 2; h++) {
                    const int n = n0 + r + h * 8;
                    __half2 hv = __floats2half2_rn(acc.c[mi][ni][h * 2] + bv.x,
                                                   acc.c[mi][ni][h * 2 + 1] + bv.y);
                    *(__half2*)(T + ((size_t)b * NN + n) * CI + ci) = hv;
                }
            }
        }
    } else {
        const int tt = t - 32;
        const int o0 = (tt >> 3) * 128, n0 = (tt & 7) * 128;
        gemm_main(acc, sm,
                  d_W3 + (size_t)(512 + o0) * CC, CC,
                  d_xp + ((size_t)b * NN + n0) * CC, CC, CC);
        #pragma unroll
        for (int mi = 0; mi < 4; mi++) {
            #pragma unroll
            for (int ni = 0; ni < 4; ni++) {
                const int r = wm * 64 + mi * 16 + (lane >> 2);
                const int col = wn * 32 + ni * 8 + (lane & 3) * 2;
                #pragma unroll
                for (int h = 0; h < 2; h++) {
                    const int o = o0 + r + h * 8;
                    const float bvv = bg[o];
                    __half2 hv = __floats2half2_rn(acc.c[mi][ni][h * 2] + bvv,
                                                   acc.c[mi][ni][h * 2 + 1] + bvv);
                    *(__half2*)(d_gp + ((size_t)b * CI + o) * NN + n0 + col) = hv;
                }
            }
        }
    }
}

// logits: C[n, m] = theta[n,:].phi[m,:], K=256, fp16 out
__global__ void __launch_bounds__(256) fgemm(void)
{
    extern __shared__ char sm[];
    const int b = blockIdx.z, n0 = blockIdx.y * 128, m0 = blockIdx.x * 128;
    Acc acc;
    gemm_main(acc, sm,
              d_th + ((size_t)b * NN + n0) * CI, CI,
              d_ph + ((size_t)b * NN + m0) * CI, CI, CI);
    EPI_SETUP();
    #pragma unroll
    for (int mi = 0; mi < 4; mi++) {
        #pragma unroll
        for (int ni = 0; ni < 4; ni++) {
            const int r = wm * 64 + mi * 16 + (lane >> 2);
            const int col = wn * 32 + ni * 8 + (lane & 3) * 2;
            #pragma unroll
            for (int h = 0; h < 2; h++) {
                const int n = n0 + r + h * 8;
                __half2 hv = __floats2half2_rn(acc.c[mi][ni][h * 2],
                                               acc.c[mi][ni][h * 2 + 1]);
                *(__half2*)(d_fh + ((size_t)b * NN + n) * NN + m0 + col) = hv;
            }
        }
    }
}

// y: C[n, c] = P[n,:].g[c,:], K=1024
__global__ void __launch_bounds__(256) ygemm(void)
{
    extern __shared__ char sm[];
    const int b = blockIdx.z, n0 = blockIdx.y * 128, c0 = blockIdx.x * 128;
    Acc acc;
    gemm_main(acc, sm,
              d_P + ((size_t)b * NN + n0) * NN, NN,
              d_gp + ((size_t)b * CI + c0) * NN, NN, NN);
    EPI_SETUP();
    #pragma unroll
    for (int mi = 0; mi < 4; mi++) {
        #pragma unroll
        for (int ni = 0; ni < 4; ni++) {
            const int r = wm * 64 + mi * 16 + (lane >> 2);
            const int col = wn * 32 + ni * 8 + (lane & 3) * 2;
            #pragma unroll
            for (int h = 0; h < 2; h++) {
                const int n = n0 + r + h * 8;
                __half2 hv = __floats2half2_rn(acc.c[mi][ni][h * 2],
                                               acc.c[mi][ni][h * 2 + 1]);
                *(__half2*)(d_y + ((size_t)b * NN + n) * CI + c0 + col) = hv;
            }
        }
    }
}

// wz: C[o, n] = Wz[o,:].y[n,:], K=256, + bias, fp16 out
__global__ void __launch_bounds__(256) zgemm(const float* __restrict__ bz)
{
    extern __shared__ char sm[];
    const int b = blockIdx.z, o0 = blockIdx.y * 128, n0 = blockIdx.x * 128;
    Acc acc;
    gemm_main(acc, sm,
              d_Wzh + (size_t)o0 * CI, CI,
              d_y + ((size_t)b * NN + n0) * CI, CI, CI);
    EPI_SETUP();
    #pragma unroll
    for (int mi = 0; mi < 4; mi++) {
        #pragma unroll
        for (int ni = 0; ni < 4; ni++) {
            const int r = wm * 64 + mi * 16 + (lane >> 2);
            const int col = wn * 32 + ni * 8 + (lane & 3) * 2;
            #pragma unroll
            for (int h = 0; h < 2; h++) {
                const int o = o0 + r + h * 8;
                const float bvv = bz[o];
                __half2 hv = __floats2half2_rn(acc.c[mi][ni][h * 2] + bvv,
                                               acc.c[mi][ni][h * 2 + 1] + bvv);
                *(__half2*)(d_wyh + ((size_t)b * CC + o) * NN + n0 + col) = hv;
            }
        }
    }
}

// ---------------------------------------------------------------------------
// Conversion kernels
// ---------------------------------------------------------------------------
__global__ void __launch_bounds__(256) convert_w(
    const float* __restrict__ Wg, const float* __restrict__ Wt, const float* __restrict__ Wp,
    const float* __restrict__ Wz)
{
    int idx = blockIdx.x * 256 + threadIdx.x;   // 768*512 + 512*256 elems
    if (idx < 768 * 512) {
        int row = idx >> 9, c = idx & 511;
        float v = (row < 256) ? Wt[row * CC + c]
                : (row < 512) ? Wp[(row - 256) * CC + c]
                              : Wg[(row - 512) * CC + c];
        d_W3[idx] = __float2half_rn(v);
    } else {
        int j = idx - 768 * 512;
        d_Wzh[j] = __float2half_rn(Wz[j]);
    }
}

// x[b][c][n] fp32 -> d_xp[b][n][c] fp16 (32x32 smem transpose)
__global__ void __launch_bounds__(256) convert_x(const float* __restrict__ x)
{
    __shared__ float t[32][33];
    const int n0 = blockIdx.x * 32, c0 = blockIdx.y * 32, b = blockIdx.z;
    const int tx = threadIdx.x, ty = threadIdx.y;   // (32, 8)
    #pragma unroll
    for (int i = 0; i < 4; i++)
        t[ty + i * 8][tx] = x[((size_t)b * CC + c0 + ty + i * 8) * NN + n0 + tx];
    __syncthreads();
    #pragma unroll
    for (int i = 0; i < 4; i++) {
        const int n = n0 + ty + i * 8, c = c0 + tx;
        d_xp[((size_t)b * NN + n) * CC + c] = __float2half_rn(t[tx][ty + i * 8]);
    }
}

// ---------------------------------------------------------------------------
// Softmax over m (1024): d_fh fp16 -> d_P fp16
// ---------------------------------------------------------------------------
__global__ void __launch_bounds__(256) softmax_kernel()
{
    const size_t row = blockIdx.x;
    const __half* p = d_fh + row * NN;
    const int tid = threadIdx.x;
    const int lane = tid & 31, warp = tid >> 5;

    union { __half2 h2[2]; uint2 u; } In;
    In.u = ((const uint2*)p)[tid];
    float4 v;
    {
        float2 a = __half22float2(In.h2[0]);
        float2 c = __half22float2(In.h2[1]);
        v = make_float4(a.x, a.y, c.x, c.y);
    }
    float m = fmaxf(fmaxf(v.x, v.y), fmaxf(v.z, v.w));
    #pragma unroll
    for (int off = 16; off; off >>= 1) m = fmaxf(m, __shfl_xor_sync(~0u, m, off));
    __shared__ float redm[8];
    if (lane == 0) redm[warp] = m;
    __syncthreads();
    float bm = redm[0];
    #pragma unroll
    for (int i = 1; i < 8; i++) bm = fmaxf(bm, redm[i]);

    v.x = expf(v.x - bm); v.y = expf(v.y - bm);
    v.z = expf(v.z - bm); v.w = expf(v.w - bm);
    float s = v.x + v.y + v.z + v.w;
    #pragma unroll
    for (int off = 16; off; off >>= 1) s += __shfl_xor_sync(~0u, s, off);
    __shared__ float reds[8];
    if (lane == 0) reds[warp] = s;
    __syncthreads();
    float bs = 0.f;
    #pragma unroll
    for (int i = 0; i < 8; i++) bs += reds[i];
    float inv = 1.f / bs;

    union { __half2 h2[2]; uint2 u; } U;
    U.h2[0] = __floats2half2_rn(v.x * inv, v.y * inv);
    U.h2[1] = __floats2half2_rn(v.z * inv, v.w * inv);
    ((uint2*)(d_P + row * NN))[tid] = U.u;
}

// ---------------------------------------------------------------------------
// BN statistics + final fuse (fp16 w_y)
// ---------------------------------------------------------------------------
__global__ void __launch_bounds__(256) bn_stats_kernel()
{
    const int ch = blockIdx.x;
    const int tid = threadIdx.x;
    float s = 0.f, s2 = 0.f;
    const __half* base = d_wyh;
    for (int i = tid; i < NB * NN / 2; i += 256) {
        int b = i / 512, n2 = i % 512;
        __half2 hv = *(const __half2*)(base + ((size_t)b * CC + ch) * NN + n2 * 2);
        float2 f2 = __half22float2(hv);
        s += f2.x + f2.y; s2 += f2.x * f2.x + f2.y * f2.y;
    }
    #pragma unroll
    for (int off = 16; off; off >>= 1) {
        s  += __shfl_xor_sync(~0u, s,  off);
        s2 += __shfl_xor_sync(~0u, s2, off);
    }
    __shared__ float rs[8], rs2[8];
    if ((tid & 31) == 0) { rs[tid >> 5] = s; rs2[tid >> 5] = s2; }
    __syncthreads();
    if (tid == 0) {
        float ts = 0.f, ts2 = 0.f;
        #pragma unroll
        for (int i = 0; i < 8; i++) { ts += rs[i]; ts2 += rs2[i]; }
        const float invM = 1.f / (float)(NB * NN);
        float mean = ts * invM;
        float var  = ts2 * invM - mean * mean;
        d_mean[ch] = mean;
        d_rstd[ch] = rsqrtf(var + EPSF);
    }
}

__global__ void __launch_bounds__(256) final_kernel(
    const float* __restrict__ x,
    const float* __restrict__ gamma, const float* __restrict__ beta,
    float* __restrict__ out)
{
    size_t i4 = (size_t)blockIdx.x * 256 + threadIdx.x;    // 4-element chunk index
    int c = (int)((i4 >> 8) & 511);
    float scale = d_rstd[c] * gamma[c];
    float shift = beta[c] - d_mean[c] * scale;
    union { __half2 h2[2]; uint2 u; } W;
    W.u = ((const uint2*)d_wyh)[i4];
    float2 w01 = __half22float2(W.h2[0]);
    float2 w23 = __half22float2(W.h2[1]);
    float4 xv = ((const float4*)x)[i4];
    float4 o;
    o.x = fmaf(w01.x, scale, shift) + xv.x;
    o.y = fmaf(w01.y, scale, shift) + xv.y;
    o.z = fmaf(w23.x, scale, shift) + xv.z;
    o.w = fmaf(w23.y, scale, shift) + xv.w;
    ((float4*)out)[i4] = o;
}

// ---------------------------------------------------------------------------
extern "C" void kernel_launch(void* const* d_in, const int* in_sizes, int n_in,
                              void* d_out, int out_size)
{
    (void)in_sizes; (void)n_in; (void)out_size;
    const float* x     = (const float*)d_in[0];
    const float* Wg    = (const float*)d_in[1];
    const float* bg    = (const float*)d_in[2];
    const float* Wt    = (const float*)d_in[3];
    const float* bt    = (const float*)d_in[4];
    const float* Wp    = (const float*)d_in[5];
    const float* bp    = (const float*)d_in[6];
    const float* Wz    = (const float*)d_in[7];
    const float* bz    = (const float*)d_in[8];
    const float* gamma = (const float*)d_in[9];
    const float* beta  = (const float*)d_in[10];
    float* out = (float*)d_out;

    cudaFuncSetAttribute(proj_all, cudaFuncAttributeMaxDynamicSharedMemorySize, SMEM_GEMM);
    cudaFuncSetAttribute(fgemm,    cudaFuncAttributeMaxDynamicSharedMemorySize, SMEM_GEMM);
    cudaFuncSetAttribute(ygemm,    cudaFuncAttributeMaxDynamicSharedMemorySize, SMEM_GEMM);
    cudaFuncSetAttribute(zgemm,    cudaFuncAttributeMaxDynamicSharedMemorySize, SMEM_GEMM);

    dim3 blk(256);
    convert_w<<<(768 * 512 + 512 * 256) / 256, blk>>>(Wg, Wt, Wp, Wz);
    convert_x<<<dim3(NN / 32, CC / 32, NB), dim3(32, 8)>>>(x);

    proj_all<<<dim3(48, 1, NB), blk, SMEM_GEMM>>>(bt, bp, bg);
    fgemm<<<dim3(8, 8, NB), blk, SMEM_GEMM>>>();
    softmax_kernel<<<NB * NN, blk>>>();
    ygemm<<<dim3(2, 8, NB), blk, SMEM_GEMM>>>();
    zgemm<<<dim3(8, 4, NB), blk, SMEM_GEMM>>>(bz);

    bn_stats_kernel<<<CC, blk>>>();
    final_kernel<<<(NB * CC * NN / 4) / 256, blk>>>(x, gamma, beta, out);
}

// round 12
// speedup vs baseline: 1.5227x; 1.0196x over previous
#include <cuda_runtime.h>
#include <cuda_fp16.h>
#include <cstdint>

#define NB 32
#define CC 512
#define CI 256
#define NN 1024
#define EPSF 1e-5f

// ---------------- scratch (device globals; no allocations allowed) ----------
__device__ __align__(128) __half d_W3[768 * CC];                   // rows: 0-255 Wt, 256-511 Wp, 512-767 Wg
__device__ __align__(128) __half d_Wzh[CC * CI];
__device__ __align__(128) __half d_xp[(size_t)NB * NN * CC];       // x^T [b][n][c]
__device__ __align__(128) __half d_th[(size_t)NB * NN * CI];       // theta [b][n][c]
__device__ __align__(128) __half d_ph[(size_t)NB * NN * CI];       // phi   [b][m][c]
__device__ __align__(128) __half d_gp[(size_t)NB * CI * NN];       // g [b][c][m]
__device__ __align__(128) __half d_fh[(size_t)NB * NN * NN];       // logits fp16 [b][n][m]
__device__ __align__(128) __half d_P[(size_t)NB * NN * NN];        // attn [b][n][m]
__device__ __align__(128) __half d_y[(size_t)NB * NN * CI];        // y [b][n][c]
__device__ __align__(128) __half d_wyh[(size_t)NB * CC * NN];      // w_y fp16 [b][c][n]
__device__ float d_mean[CC], d_rstd[CC];

// ---------------- PTX helpers ----------------------------------------------
__device__ __forceinline__ uint32_t smem_u32_of(const void* p) {
    uint32_t a;
    asm("{ .reg .u64 t; cvta.to.shared.u64 t, %1; cvt.u32.u64 %0, t; }" : "=r"(a) : "l"(p));
    return a;
}
#define CP_ASYNC16(dst, src) \
    asm volatile("cp.async.cg.shared.global [%0], [%1], 16;" :: "r"(dst), "l"(src))
#define CP_COMMIT() asm volatile("cp.async.commit_group;" ::: "memory")
#define CP_WAIT1()  asm volatile("cp.async.wait_group 1;" ::: "memory")
#define LDSM4(r0, r1, r2, r3, addr) \
    asm volatile("ldmatrix.sync.aligned.m8n8.x4.shared.b16 {%0,%1,%2,%3}, [%4];" \
                 : "=r"(r0), "=r"(r1), "=r"(r2), "=r"(r3) : "r"(addr))
#define MMA16816(d, a, b0, b1) \
    asm volatile("mma.sync.aligned.m16n8k16.row.col.f32.f16.f16.f32 " \
                 "{%0,%1,%2,%3}, {%4,%5,%6,%7}, {%8,%9}, {%0,%1,%2,%3};" \
                 : "+f"((d)[0]), "+f"((d)[1]), "+f"((d)[2]), "+f"((d)[3]) \
                 : "r"((a)[0]), "r"((a)[1]), "r"((a)[2]), "r"((a)[3]), "r"(b0), "r"(b1))

// ---------------- GEMM core -------------------------------------------------
// C[128 x 128] = A[128 x K] . B[128 x K]^T,  A/B row-major K-contiguous fp16.
// 128 threads (4 warps), warp grid 2(M) x 2(N), warp tile 64x64, BK=64,
// 3-stage cp.async, 96KB smem -> 2 CTAs/SM.
#define NT 128
#define BK 64
#define STAGES 3
#define STAGE_B 32768          // A 16KB + B 16KB
#define SMEM_GEMM (STAGES * STAGE_B)

struct Acc { float c[4][8][4]; };

__device__ __forceinline__ void load_stage(char* sm, int s,
                                           const __half* A, int lda,
                                           const __half* B, int ldb,
                                           int kt, int tid) {
    const char* ag = (const char*)(A + (size_t)kt * BK);
    const char* bg = (const char*)(B + (size_t)kt * BK);
    uint32_t sa = smem_u32_of(sm + s * STAGE_B);
    uint32_t sb = sa + 16384;
    #pragma unroll
    for (int i = 0; i < 8; i++) {
        int L = tid + i * NT;
        int r = L >> 3, c8 = L & 7;
        uint32_t off = (uint32_t)(r * 128 + ((c8 ^ (r & 7)) * 16));
        CP_ASYNC16(sa + off, ag + (size_t)r * lda * 2 + c8 * 16);
        CP_ASYNC16(sb + off, bg + (size_t)r * ldb * 2 + c8 * 16);
    }
    CP_COMMIT();
}

__device__ __forceinline__ void compute_stage(char* sm, int s, Acc& acc,
                                              int wm, int wn, int lane) {
    uint32_t sa = smem_u32_of(sm + s * STAGE_B);
    uint32_t sb = sa + 16384;
    const int lr = lane & 15, lc = lane >> 4;
    #pragma unroll
    for (int ks = 0; ks < 4; ks++) {
        uint32_t a[4][4], bf[4][4];
        const int c8 = ks * 2 + lc;
        #pragma unroll
        for (int mi = 0; mi < 4; mi++) {
            int row = wm * 64 + mi * 16 + lr;
            uint32_t addr = sa + (uint32_t)(row * 128 + ((c8 ^ (row & 7)) * 16));
            LDSM4(a[mi][0], a[mi][1], a[mi][2], a[mi][3], addr);
        }
        #pragma unroll
        for (int nj = 0; nj < 4; nj++) {
            int row = wn * 64 + nj * 16 + lr;
            uint32_t addr = sb + (uint32_t)(row * 128 + ((c8 ^ (row & 7)) * 16));
            LDSM4(bf[nj][0], bf[nj][1], bf[nj][2], bf[nj][3], addr);
        }
        #pragma unroll
        for (int mi = 0; mi < 4; mi++)
            #pragma unroll
            for (int ni = 0; ni < 8; ni++)
                MMA16816(acc.c[mi][ni], a[mi], bf[ni >> 1][ni & 1], bf[ni >> 1][(ni & 1) + 2]);
    }
}

__device__ __forceinline__ void gemm_main(Acc& acc, char* sm,
                                          const __half* A, int lda,
                                          const __half* B, int ldb, int K) {
    const int tid = threadIdx.x;
    const int lane = tid & 31, wid = tid >> 5;
    const int wm = wid & 1, wn = wid >> 1;
    #pragma unroll
    for (int mi = 0; mi < 4; mi++)
        #pragma unroll
        for (int ni = 0; ni < 8; ni++)
            #pragma unroll
            for (int k = 0; k < 4; k++) acc.c[mi][ni][k] = 0.f;

    const int nk = K / BK;
    #pragma unroll
    for (int s = 0; s < STAGES - 1; s++) load_stage(sm, s, A, lda, B, ldb, s, tid);
    for (int k = 0; k < nk; k++) {
        CP_WAIT1();
        __syncthreads();
        if (k + STAGES - 1 < nk)
            load_stage(sm, (k + STAGES - 1) % STAGES, A, lda, B, ldb, k + STAGES - 1, tid);
        compute_stage(sm, k % STAGES, acc, wm, wn, lane);
    }
}

// thread's accum coordinates: row = wm*64 + mi*16 + (lane>>2) + h*8
//                             col = wn*64 + ni*8 + (lane&3)*2
#define EPI_SETUP() \
    const int lane = threadIdx.x & 31, wid = threadIdx.x >> 5; \
    const int wm = wid & 1, wn = wid >> 1; (void)wm; (void)wn;

// ---------------------------------------------------------------------------
// GEMM kernels
// ---------------------------------------------------------------------------
// Merged projection kernel. Tile id t = blockIdx.x:
//   t in [0, 32):  theta/phi: C[n, o] = x'[n,:].W3[o,:]; o0=(t>>3)*128, n0=(t&7)*128
//   t in [32, 48): g:         C[o, n] = Wg[o,:].x'[n,:]; o0=((t-32)>>3)*128, n0=((t-32)&7)*128
__global__ void __launch_bounds__(NT) proj_all(
    const float* __restrict__ bt, const float* __restrict__ bp,
    const float* __restrict__ bg)
{
    extern __shared__ char sm[];
    const int b = blockIdx.z;
    const int t = blockIdx.x;
    Acc acc;
    EPI_SETUP();

    if (t < 32) {
        const int o0 = (t >> 3) * 128, n0 = (t & 7) * 128;
        gemm_main(acc, sm,
                  d_xp + ((size_t)b * NN + n0) * CC, CC,
                  d_W3 + (size_t)o0 * CC, CC, CC);
        const bool is_t = (o0 < 256);
        const float* bias = is_t ? bt : bp;
        __half* T = is_t ? d_th : d_ph;
        #pragma unroll
        for (int mi = 0; mi < 4; mi++) {
            #pragma unroll
            for (int ni = 0; ni < 8; ni++) {
                const int r = wm * 64 + mi * 16 + (lane >> 2);
                const int ci = (o0 & 255) + wn * 64 + ni * 8 + (lane & 3) * 2;
                const float2 bv = *(const float2*)&bias[ci];
                #pragma unroll
                for (int h = 0; h < 2; h++) {
                    const int n = n0 + r + h * 8;
                    __half2 hv = __floats2half2_rn(acc.c[mi][ni][h * 2] + bv.x,
                                                   acc.c[mi][ni][h * 2 + 1] + bv.y);
                    *(__half2*)(T + ((size_t)b * NN + n) * CI + ci) = hv;
                }
            }
        }
    } else {
        const int tt = t - 32;
        const int o0 = (tt >> 3) * 128, n0 = (tt & 7) * 128;
        gemm_main(acc, sm,
                  d_W3 + (size_t)(512 + o0) * CC, CC,
                  d_xp + ((size_t)b * NN + n0) * CC, CC, CC);
        #pragma unroll
        for (int mi = 0; mi < 4; mi++) {
            #pragma unroll
            for (int ni = 0; ni < 8; ni++) {
                const int r = wm * 64 + mi * 16 + (lane >> 2);
                const int col = wn * 64 + ni * 8 + (lane & 3) * 2;
                #pragma unroll
                for (int h = 0; h < 2; h++) {
                    const int o = o0 + r + h * 8;
                    const float bvv = bg[o];
                    __half2 hv = __floats2half2_rn(acc.c[mi][ni][h * 2] + bvv,
                                                   acc.c[mi][ni][h * 2 + 1] + bvv);
                    *(__half2*)(d_gp + ((size_t)b * CI + o) * NN + n0 + col) = hv;
                }
            }
        }
    }
}

// logits: C[n, m] = theta[n,:].phi[m,:], K=256, fp16 out
__global__ void __launch_bounds__(NT) fgemm(void)
{
    extern __shared__ char sm[];
    const int b = blockIdx.z, n0 = blockIdx.y * 128, m0 = blockIdx.x * 128;
    Acc acc;
    gemm_main(acc, sm,
              d_th + ((size_t)b * NN + n0) * CI, CI,
              d_ph + ((size_t)b * NN + m0) * CI, CI, CI);
    EPI_SETUP();
    #pragma unroll
    for (int mi = 0; mi < 4; mi++) {
        #pragma unroll
        for (int ni = 0; ni < 8; ni++) {
            const int r = wm * 64 + mi * 16 + (lane >> 2);
            const int col = wn * 64 + ni * 8 + (lane & 3) * 2;
            #pragma unroll
            for (int h = 0; h < 2; h++) {
                const int n = n0 + r + h * 8;
                __half2 hv = __floats2half2_rn(acc.c[mi][ni][h * 2],
                                               acc.c[mi][ni][h * 2 + 1]);
                *(__half2*)(d_fh + ((size_t)b * NN + n) * NN + m0 + col) = hv;
            }
        }
    }
}

// y: C[n, c] = P[n,:].g[c,:], K=1024
__global__ void __launch_bounds__(NT) ygemm(void)
{
    extern __shared__ char sm[];
    const int b = blockIdx.z, n0 = blockIdx.y * 128, c0 = blockIdx.x * 128;
    Acc acc;
    gemm_main(acc, sm,
              d_P + ((size_t)b * NN + n0) * NN, NN,
              d_gp + ((size_t)b * CI + c0) * NN, NN, NN);
    EPI_SETUP();
    #pragma unroll
    for (int mi = 0; mi < 4; mi++) {
        #pragma unroll
        for (int ni = 0; ni < 8; ni++) {
            const int r = wm * 64 + mi * 16 + (lane >> 2);
            const int col = wn * 64 + ni * 8 + (lane & 3) * 2;
            #pragma unroll
            for (int h = 0; h < 2; h++) {
                const int n = n0 + r + h * 8;
                __half2 hv = __floats2half2_rn(acc.c[mi][ni][h * 2],
                                               acc.c[mi][ni][h * 2 + 1]);
                *(__half2*)(d_y + ((size_t)b * NN + n) * CI + c0 + col) = hv;
            }
        }
    }
}

// wz: C[o, n] = Wz[o,:].y[n,:], K=256, + bias, fp16 out
__global__ void __launch_bounds__(NT) zgemm(const float* __restrict__ bz)
{
    extern __shared__ char sm[];
    const int b = blockIdx.z, o0 = blockIdx.y * 128, n0 = blockIdx.x * 128;
    Acc acc;
    gemm_main(acc, sm,
              d_Wzh + (size_t)o0 * CI, CI,
              d_y + ((size_t)b * NN + n0) * CI, CI, CI);
    EPI_SETUP();
    #pragma unroll
    for (int mi = 0; mi < 4; mi++) {
        #pragma unroll
        for (int ni = 0; ni < 8; ni++) {
            const int r = wm * 64 + mi * 16 + (lane >> 2);
            const int col = wn * 64 + ni * 8 + (lane & 3) * 2;
            #pragma unroll
            for (int h = 0; h < 2; h++) {
                const int o = o0 + r + h * 8;
                const float bvv = bz[o];
                __half2 hv = __floats2half2_rn(acc.c[mi][ni][h * 2] + bvv,
                                               acc.c[mi][ni][h * 2 + 1] + bvv);
                *(__half2*)(d_wyh + ((size_t)b * CC + o) * NN + n0 + col) = hv;
            }
        }
    }
}

// ---------------------------------------------------------------------------
// Conversion kernels
// ---------------------------------------------------------------------------
__global__ void __launch_bounds__(256) convert_w(
    const float* __restrict__ Wg, const float* __restrict__ Wt, const float* __restrict__ Wp,
    const float* __restrict__ Wz)
{
    int idx = blockIdx.x * 256 + threadIdx.x;   // 768*512 + 512*256 elems
    if (idx < 768 * 512) {
        int row = idx >> 9, c = idx & 511;
        float v = (row < 256) ? Wt[row * CC + c]
                : (row < 512) ? Wp[(row - 256) * CC + c]
                              : Wg[(row - 512) * CC + c];
        d_W3[idx] = __float2half_rn(v);
    } else {
        int j = idx - 768 * 512;
        d_Wzh[j] = __float2half_rn(Wz[j]);
    }
}

// x[b][c][n] fp32 -> d_xp[b][n][c] fp16 (32x32 smem transpose)
__global__ void __launch_bounds__(256) convert_x(const float* __restrict__ x)
{
    __shared__ float t[32][33];
    const int n0 = blockIdx.x * 32, c0 = blockIdx.y * 32, b = blockIdx.z;
    const int tx = threadIdx.x, ty = threadIdx.y;   // (32, 8)
    #pragma unroll
    for (int i = 0; i < 4; i++)
        t[ty + i * 8][tx] = x[((size_t)b * CC + c0 + ty + i * 8) * NN + n0 + tx];
    __syncthreads();
    #pragma unroll
    for (int i = 0; i < 4; i++) {
        const int n = n0 + ty + i * 8, c = c0 + tx;
        d_xp[((size_t)b * NN + n) * CC + c] = __float2half_rn(t[tx][ty + i * 8]);
    }
}

// ---------------------------------------------------------------------------
// Softmax over m (1024): d_fh fp16 -> d_P fp16
// ---------------------------------------------------------------------------
__global__ void __launch_bounds__(256) softmax_kernel()
{
    const size_t row = blockIdx.x;
    const __half* p = d_fh + row * NN;
    const int tid = threadIdx.x;
    const int lane = tid & 31, warp = tid >> 5;

    union { __half2 h2[2]; uint2 u; } In;
    In.u = ((const uint2*)p)[tid];
    float4 v;
    {
        float2 a = __half22float2(In.h2[0]);
        float2 c = __half22float2(In.h2[1]);
        v = make_float4(a.x, a.y, c.x, c.y);
    }
    float m = fmaxf(fmaxf(v.x, v.y), fmaxf(v.z, v.w));
    #pragma unroll
    for (int off = 16; off; off >>= 1) m = fmaxf(m, __shfl_xor_sync(~0u, m, off));
    __shared__ float redm[8];
    if (lane == 0) redm[warp] = m;
    __syncthreads();
    float bm = redm[0];
    #pragma unroll
    for (int i = 1; i < 8; i++) bm = fmaxf(bm, redm[i]);

    v.x = expf(v.x - bm); v.y = expf(v.y - bm);
    v.z = expf(v.z - bm); v.w = expf(v.w - bm);
    float s = v.x + v.y + v.z + v.w;
    #pragma unroll
    for (int off = 16; off; off >>= 1) s += __shfl_xor_sync(~0u, s, off);
    __shared__ float reds[8];
    if (lane == 0) reds[warp] = s;
    __syncthreads();
    float bs = 0.f;
    #pragma unroll
    for (int i = 0; i < 8; i++) bs += reds[i];
    float inv = 1.f / bs;

    union { __half2 h2[2]; uint2 u; } U;
    U.h2[0] = __floats2half2_rn(v.x * inv, v.y * inv);
    U.h2[1] = __floats2half2_rn(v.z * inv, v.w * inv);
    ((uint2*)(d_P + row * NN))[tid] = U.u;
}

// ---------------------------------------------------------------------------
// BN statistics + final fuse (fp16 w_y)
// ---------------------------------------------------------------------------
__global__ void __launch_bounds__(256) bn_stats_kernel()
{
    const int ch = blockIdx.x;
    const int tid = threadIdx.x;
    float s = 0.f, s2 = 0.f;
    const __half* base = d_wyh;
    for (int i = tid; i < NB * NN / 2; i += 256) {
        int b = i / 512, n2 = i % 512;
        __half2 hv = *(const __half2*)(base + ((size_t)b * CC + ch) * NN + n2 * 2);
        float2 f2 = __half22float2(hv);
        s += f2.x + f2.y; s2 += f2.x * f2.x + f2.y * f2.y;
    }
    #pragma unroll
    for (int off = 16; off; off >>= 1) {
        s  += __shfl_xor_sync(~0u, s,  off);
        s2 += __shfl_xor_sync(~0u, s2, off);
    }
    __shared__ float rs[8], rs2[8];
    if ((tid & 31) == 0) { rs[tid >> 5] = s; rs2[tid >> 5] = s2; }
    __syncthreads();
    if (tid == 0) {
        float ts = 0.f, ts2 = 0.f;
        #pragma unroll
        for (int i = 0; i < 8; i++) { ts += rs[i]; ts2 += rs2[i]; }
        const float invM = 1.f / (float)(NB * NN);
        float mean = ts * invM;
        float var  = ts2 * invM - mean * mean;
        d_mean[ch] = mean;
        d_rstd[ch] = rsqrtf(var + EPSF);
    }
}

__global__ void __launch_bounds__(256) final_kernel(
    const float* __restrict__ x,
    const float* __restrict__ gamma, const float* __restrict__ beta,
    float* __restrict__ out)
{
    size_t i4 = (size_t)blockIdx.x * 256 + threadIdx.x;    // 4-element chunk index
    int c = (int)((i4 >> 8) & 511);
    float scale = d_rstd[c] * gamma[c];
    float shift = beta[c] - d_mean[c] * scale;
    union { __half2 h2[2]; uint2 u; } W;
    W.u = ((const uint2*)d_wyh)[i4];
    float2 w01 = __half22float2(W.h2[0]);
    float2 w23 = __half22float2(W.h2[1]);
    float4 xv = ((const float4*)x)[i4];
    float4 o;
    o.x = fmaf(w01.x, scale, shift) + xv.x;
    o.y = fmaf(w01.y, scale, shift) + xv.y;
    o.z = fmaf(w23.x, scale, shift) + xv.z;
    o.w = fmaf(w23.y, scale, shift) + xv.w;
    ((float4*)out)[i4] = o;
}

// ---------------------------------------------------------------------------
extern "C" void kernel_launch(void* const* d_in, const int* in_sizes, int n_in,
                              void* d_out, int out_size)
{
    (void)in_sizes; (void)n_in; (void)out_size;
    const float* x     = (const float*)d_in[0];
    const float* Wg    = (const float*)d_in[1];
    const float* bg    = (const float*)d_in[2];
    const float* Wt    = (const float*)d_in[3];
    const float* bt    = (const float*)d_in[4];
    const float* Wp    = (const float*)d_in[5];
    const float* bp    = (const float*)d_in[6];
    const float* Wz    = (const float*)d_in[7];
    const float* bz    = (const float*)d_in[8];
    const float* gamma = (const float*)d_in[9];
    const float* beta  = (const float*)d_in[10];
    float* out = (float*)d_out;

    cudaFuncSetAttribute(proj_all, cudaFuncAttributeMaxDynamicSharedMemorySize, SMEM_GEMM);
    cudaFuncSetAttribute(fgemm,    cudaFuncAttributeMaxDynamicSharedMemorySize, SMEM_GEMM);
    cudaFuncSetAttribute(ygemm,    cudaFuncAttributeMaxDynamicSharedMemorySize, SMEM_GEMM);
    cudaFuncSetAttribute(zgemm,    cudaFuncAttributeMaxDynamicSharedMemorySize, SMEM_GEMM);

    dim3 blk(256);
    dim3 gblk(NT);
    convert_w<<<(768 * 512 + 512 * 256) / 256, blk>>>(Wg, Wt, Wp, Wz);
    convert_x<<<dim3(NN / 32, CC / 32, NB), dim3(32, 8)>>>(x);

    proj_all<<<dim3(48, 1, NB), gblk, SMEM_GEMM>>>(bt, bp, bg);
    fgemm<<<dim3(8, 8, NB), gblk, SMEM_GEMM>>>();
    softmax_kernel<<<NB * NN, blk>>>();
    ygemm<<<dim3(2, 8, NB), gblk, SMEM_GEMM>>>();
    zgemm<<<dim3(8, 4, NB), gblk, SMEM_GEMM>>>(bz);

    bn_stats_kernel<<<CC, blk>>>();
    final_kernel<<<(NB * CC * NN / 4) / 256, blk>>>(x, gamma, beta, out);
}